// round 9
// baseline (speedup 1.0000x reference)
#include <cuda_runtime.h>
#include <cstdint>
#include <math.h>

#define BSZ 64
#define TSZ 512
#define ESZ 256
#define USZ 512
#define GSZ 2048
#define NBLK 128
#define NBLK_DIR 64

// Scratch (static device allocations only)
__device__ float g_xz[(size_t)2 * TSZ * 4 * BSZ * USZ];   // [dir][t][g][b][u]
__device__ float g_h[2][2][USZ * BSZ];                    // [dir][parity][u][b]
__device__ unsigned g_bar_cnt[64];                        // [dir*32]
__device__ unsigned g_bar_gen[64];                        // [dir*32]

// ---- packed f32x2 helpers ----
__device__ __forceinline__ void ffma2(unsigned long long& d,
                                      unsigned long long a,
                                      unsigned long long b) {
    asm("fma.rn.f32x2 %0, %1, %2, %0;" : "+l"(d) : "l"(a), "l"(b));
}
__device__ __forceinline__ void addf2(unsigned long long& d, unsigned long long a) {
    asm("add.rn.f32x2 %0, %0, %1;" : "+l"(d) : "l"(a));
}
__device__ __forceinline__ unsigned long long splat2(float x) {
    unsigned long long r;
    unsigned u = __float_as_uint(x);
    asm("mov.b64 %0, {%1, %1};" : "=l"(r) : "r"(u));
    return r;
}
__device__ __forceinline__ unsigned long long pack2(float lo, float hi) {
    unsigned long long r;
    asm("mov.b64 %0, {%1, %2};" : "=l"(r) : "r"(__float_as_uint(lo)), "r"(__float_as_uint(hi)));
    return r;
}
__device__ __forceinline__ void unpack2(unsigned long long v, float& lo, float& hi) {
    unsigned a, b;
    asm("mov.b64 {%0, %1}, %2;" : "=r"(a), "=r"(b) : "l"(v));
    lo = __uint_as_float(a); hi = __uint_as_float(b);
}

__device__ __forceinline__ float sigf(float x) {
    return __fdividef(1.f, 1.f + __expf(-x));
}
__device__ __forceinline__ float tanhf_(float x) {
    return __fdividef(2.f, 1.f + __expf(-2.f * x)) - 1.f;
}

__device__ __forceinline__ void grid_barrier(int dir) {
    __syncthreads();
    if (threadIdx.x == 0) {
        __threadfence();
        unsigned* cnt = &g_bar_cnt[dir * 32];
        unsigned* gen = &g_bar_gen[dir * 32];
        unsigned g0 = atomicAdd(gen, 0u);
        unsigned a = atomicAdd(cnt, 1u);
        if (a == NBLK_DIR - 1) {
            atomicExch(cnt, 0u);
            __threadfence();
            atomicAdd(gen, 1u);
        } else {
            while (atomicAdd(gen, 0u) == g0) { __nanosleep(32); }
        }
        __threadfence();
    }
    __syncthreads();
}

// ---------------------------------------------------------------------------
// Kernel 1: xz[dir][t][g][b][u] = (emb[idx[b][t]] @ W_dir + b_dir)
// 128x128 tile, 256 threads, FFMA2 with row-pair lanes.
// ---------------------------------------------------------------------------
__global__ void __launch_bounds__(256) xz_gemm_kernel(
    const int* __restrict__ idx, const float* __restrict__ emb,
    const float* __restrict__ Wf, const float* __restrict__ bf,
    const float* __restrict__ Wb, const float* __restrict__ bb)
{
    const int dir = blockIdx.z;
    const float* __restrict__ W    = dir ? Wb : Wf;
    const float* __restrict__ bias = dir ? bb : bf;
    float* __restrict__ xz = g_xz + (size_t)dir * TSZ * 4 * BSZ * USZ;

    __shared__ float As[16 * 128];
    __shared__ float Bs[16 * 128];
    __shared__ int rowv[128];

    const int tid   = threadIdx.x;
    const int rbase = blockIdx.y * 128;   // rows r = t*64 + b
    const int nbase = blockIdx.x * 128;   // cols n = g*512 + u

    if (tid < 128) {
        int r = rbase + tid;
        int t = r >> 6, b = r & 63;
        rowv[tid] = idx[b * TSZ + t];
    }
    __syncthreads();

    const int ty = tid >> 4, tx = tid & 15;
    unsigned long long acc2[4][8];   // lanes = row pairs (ty*8+2rp, +1); cols tx+16j
#pragma unroll
    for (int i = 0; i < 4; i++)
#pragma unroll
        for (int j = 0; j < 8; j++) acc2[i][j] = 0ull;

    const int lm  = tid >> 1;
    const int lkq = (tid & 1) * 8;
    const int lrow = rowv[lm];
    const int lk  = tid >> 4;
    const int lc  = (tid & 15) * 8;

    for (int kt = 0; kt < ESZ; kt += 16) {
        float4 a0 = *(const float4*)&emb[(size_t)lrow * ESZ + kt + lkq];
        float4 a1 = *(const float4*)&emb[(size_t)lrow * ESZ + kt + lkq + 4];
        float4 b0 = *(const float4*)&W[(size_t)(kt + lk) * GSZ + nbase + lc];
        float4 b1 = *(const float4*)&W[(size_t)(kt + lk) * GSZ + nbase + lc + 4];

        As[(lkq + 0) * 128 + lm] = a0.x;
        As[(lkq + 1) * 128 + lm] = a0.y;
        As[(lkq + 2) * 128 + lm] = a0.z;
        As[(lkq + 3) * 128 + lm] = a0.w;
        As[(lkq + 4) * 128 + lm] = a1.x;
        As[(lkq + 5) * 128 + lm] = a1.y;
        As[(lkq + 6) * 128 + lm] = a1.z;
        As[(lkq + 7) * 128 + lm] = a1.w;
        *(float4*)&Bs[lk * 128 + lc]     = b0;
        *(float4*)&Bs[lk * 128 + lc + 4] = b1;
        __syncthreads();

#pragma unroll
        for (int k = 0; k < 16; ++k) {
            ulonglong2 ra01 = *(const ulonglong2*)&As[k * 128 + ty * 8];
            ulonglong2 ra23 = *(const ulonglong2*)&As[k * 128 + ty * 8 + 4];
            const float* bs = &Bs[k * 128 + tx];
            float bj[8];
#pragma unroll
            for (int j = 0; j < 8; ++j) bj[j] = bs[16 * j];
#pragma unroll
            for (int j = 0; j < 8; ++j) {
                unsigned long long s = splat2(bj[j]);
                ffma2(acc2[0][j], ra01.x, s);
                ffma2(acc2[1][j], ra01.y, s);
                ffma2(acc2[2][j], ra23.x, s);
                ffma2(acc2[3][j], ra23.y, s);
            }
        }
        __syncthreads();
    }

    // epilogue: write [t][g][b][u]
    const int r0 = rbase + ty * 8;
    const int t  = r0 >> 6;
    const int b0 = r0 & 63;
#pragma unroll
    for (int j = 0; j < 8; ++j) {
        int n = nbase + tx + 16 * j;
        int g = n >> 9, u = n & 511;
        float bv = bias[n];
        float* base = &xz[(((size_t)t * 4 + g) * BSZ) * USZ + u];
#pragma unroll
        for (int rp = 0; rp < 4; ++rp) {
            float lo, hi;
            unpack2(acc2[rp][j], lo, hi);
            base[(size_t)(b0 + 2 * rp) * USZ]     = lo + bv;
            base[(size_t)(b0 + 2 * rp + 1) * USZ] = hi + bv;
        }
    }
}

// ---------------------------------------------------------------------------
// Kernel 2: persistent bidirectional LSTM scan.
// 128 blocks x 256 threads. Block = (dir, 8 units). 4-way k split:
// tid = kq*64 + r;  r = up*16 + bg;  thread covers units (u0,u0+1) packed in
// f32x2 lanes x 4 gates x 4 batches. U pre-packed as u64 pairs in smem.
// ---------------------------------------------------------------------------
__global__ void __launch_bounds__(256) lstm_scan_kernel(
    const int* __restrict__ idx,
    const float* __restrict__ Uf, const float* __restrict__ Ub,
    float* __restrict__ out)
{
    extern __shared__ float smem[];
    unsigned long long* Us2 = (unsigned long long*)smem;        // [k][up][g] u64 pairs, 64KB
    float* hs = smem + 16384;                                   // [k][b], 128KB
    unsigned long long* red = (unsigned long long*)(smem + 16384 + 32768); // [3][64][16], 24KB
    unsigned long long* msk = red + 3 * 64 * 16;                // [512], 4KB

    const int tid    = threadIdx.x;
    const int kq     = tid >> 6;        // 0..3
    const int r      = tid & 63;
    const int up     = r >> 4;          // 0..3
    const int bg     = r & 15;          // 4 batches each
    const int bid    = blockIdx.x;
    const int dir    = bid >> 6;
    const int ublock = bid & 63;
    const int u0     = ublock * 8 + up * 2;   // lanes: (u0, u0+1)
    const float* __restrict__ Um = dir ? Ub : Uf;
    const float* __restrict__ xz = g_xz + (size_t)dir * TSZ * 4 * BSZ * USZ;

    // one-time: U pairs into smem: Us2[(k*4+up)*4+g] = (U[k][g*512+u0], U[k][g*512+u0+1])
    for (int i = tid; i < 512 * 16; i += 256) {
        int k  = i >> 4;
        int pu = (i >> 2) & 3;
        int g  = i & 3;
        float2 v = *(const float2*)&Um[(size_t)k * GSZ + g * USZ + ublock * 8 + pu * 2];
        Us2[i] = pack2(v.x, v.y);
    }
    // one-time: masks
    for (int tt = tid * 2; tt < tid * 2 + 2; ++tt) {
        unsigned long long m = 0ull;
        for (int b = 0; b < 64; ++b)
            if (idx[b * TSZ + tt] != 0) m |= (1ull << b);
        msk[tt] = m;
    }
    // init h parity-0 (kq0 threads cover all (u, b))
    if (kq == 0) {
        float4 z4 = { 0.f, 0.f, 0.f, 0.f };
        *(float4*)&g_h[dir][0][u0 * BSZ + bg * 4]       = z4;
        *(float4*)&g_h[dir][0][(u0 + 1) * BSZ + bg * 4] = z4;
    }
    grid_barrier(dir);

    float c_st[2][4] = {{0.f,0.f,0.f,0.f},{0.f,0.f,0.f,0.f}};
    float h_st[2][4] = {{0.f,0.f,0.f,0.f},{0.f,0.f,0.f,0.f}};

    const float* hbase = hs + (kq * 128) * 64 + bg * 4;
    const ulonglong2* ubase = (const ulonglong2*)Us2 + ((size_t)(kq * 128) * 4 + up) * 2;

    for (int s = 0; s < TSZ; ++s) {
        const int t   = dir ? (TSZ - 1 - s) : s;
        const int cur = s & 1, nxt = cur ^ 1;

        // stage h [512][64] into smem
        {
            const float4* src = (const float4*)&g_h[dir][cur][0];
            float4* dst = (float4*)hs;
#pragma unroll
            for (int i = 0; i < 32; ++i)
                dst[tid + i * 256] = src[tid + i * 256];
        }

        // acc init: kq0 folds xz (u64 load = exactly the unit-pair lanes)
        unsigned long long acc2[4][4];   // [batch][gate], lanes = (u0,u0+1)
        if (kq == 0) {
            const float* xzt = xz + ((size_t)t * 4) * BSZ * USZ;
#pragma unroll
            for (int g = 0; g < 4; ++g)
#pragma unroll
                for (int bi = 0; bi < 4; ++bi)
                    acc2[bi][g] = *(const unsigned long long*)
                        &xzt[((size_t)g * BSZ + bg * 4 + bi) * USZ + u0];
        } else {
#pragma unroll
            for (int g = 0; g < 4; ++g)
#pragma unroll
                for (int bi = 0; bi < 4; ++bi) acc2[bi][g] = 0ull;
        }
        __syncthreads();

        // inner loop: 128 k per thread
        {
            const float* hptr = hbase;
            const ulonglong2* uptr = ubase;
#pragma unroll 4
            for (int k = 0; k < 128; ++k) {
                float4 hv = *(const float4*)hptr; hptr += 64;
                ulonglong2 uv01 = uptr[0];
                ulonglong2 uv23 = uptr[1];
                uptr += 8;
                unsigned long long s0 = splat2(hv.x);
                unsigned long long s1 = splat2(hv.y);
                unsigned long long s2 = splat2(hv.z);
                unsigned long long s3 = splat2(hv.w);
                ffma2(acc2[0][0], s0, uv01.x); ffma2(acc2[0][1], s0, uv01.y);
                ffma2(acc2[0][2], s0, uv23.x); ffma2(acc2[0][3], s0, uv23.y);
                ffma2(acc2[1][0], s1, uv01.x); ffma2(acc2[1][1], s1, uv01.y);
                ffma2(acc2[1][2], s1, uv23.x); ffma2(acc2[1][3], s1, uv23.y);
                ffma2(acc2[2][0], s2, uv01.x); ffma2(acc2[2][1], s2, uv01.y);
                ffma2(acc2[2][2], s2, uv23.x); ffma2(acc2[2][3], s2, uv23.y);
                ffma2(acc2[3][0], s3, uv01.x); ffma2(acc2[3][1], s3, uv01.y);
                ffma2(acc2[3][2], s3, uv23.x); ffma2(acc2[3][3], s3, uv23.y);
            }
        }

        // reduction
        if (kq > 0) {
            unsigned long long* rp = red + ((size_t)(kq - 1) * 64 + r) * 16;
#pragma unroll
            for (int bi = 0; bi < 4; ++bi)
#pragma unroll
                for (int g = 0; g < 4; ++g) rp[bi * 4 + g] = acc2[bi][g];
        }
        __syncthreads();

        if (kq == 0) {
#pragma unroll
            for (int q = 0; q < 3; ++q) {
                const unsigned long long* rp = red + ((size_t)q * 64 + r) * 16;
#pragma unroll
                for (int bi = 0; bi < 4; ++bi)
#pragma unroll
                    for (int g = 0; g < 4; ++g) addf2(acc2[bi][g], rp[bi * 4 + g]);
            }

            const unsigned long long mw = msk[t];
#pragma unroll
            for (int bi = 0; bi < 4; ++bi) {
                int b = bg * 4 + bi;
                float zA[4], zB[4];
#pragma unroll
                for (int g = 0; g < 4; ++g) unpack2(acc2[bi][g], zA[g], zB[g]);
                bool m = (mw >> b) & 1ull;
                {
                    float ig = sigf(zA[0]), fg = sigf(zA[1]);
                    float gg = tanhf_(zA[2]), og = sigf(zA[3]);
                    float cn = fg * c_st[0][bi] + ig * gg;
                    float hn = og * tanhf_(cn);
                    if (m) { c_st[0][bi] = cn; h_st[0][bi] = hn; }
                }
                {
                    float ig = sigf(zB[0]), fg = sigf(zB[1]);
                    float gg = tanhf_(zB[2]), og = sigf(zB[3]);
                    float cn = fg * c_st[1][bi] + ig * gg;
                    float hn = og * tanhf_(cn);
                    if (m) { c_st[1][bi] = cn; h_st[1][bi] = hn; }
                }
                float2 hv = { h_st[0][bi], h_st[1][bi] };
                *(float2*)&out[((size_t)b * TSZ + t) * 1024 + dir * USZ + u0] = hv;
            }
            float4 h0 = { h_st[0][0], h_st[0][1], h_st[0][2], h_st[0][3] };
            float4 h1 = { h_st[1][0], h_st[1][1], h_st[1][2], h_st[1][3] };
            *(float4*)&g_h[dir][nxt][u0 * BSZ + bg * 4]       = h0;
            *(float4*)&g_h[dir][nxt][(u0 + 1) * BSZ + bg * 4] = h1;
        }
        grid_barrier(dir);
    }

    // final states
    if (kq == 0) {
        const size_t H0 = (size_t)BSZ * TSZ * 1024;
        const size_t C0 = H0 + (size_t)BSZ * 1024;
#pragma unroll
        for (int bi = 0; bi < 4; ++bi) {
            int b = bg * 4 + bi;
            float2 hv = { h_st[0][bi], h_st[1][bi] };
            float2 cv = { c_st[0][bi], c_st[1][bi] };
            *(float2*)&out[H0 + (size_t)b * 1024 + dir * USZ + u0] = hv;
            *(float2*)&out[C0 + (size_t)b * 1024 + dir * USZ + u0] = cv;
        }
    }
}

// ---------------------------------------------------------------------------
extern "C" void kernel_launch(void* const* d_in, const int* in_sizes, int n_in,
                              void* d_out, int out_size)
{
    const int*   idx = (const int*)  d_in[0];
    const float* emb = (const float*)d_in[1];
    const float* Wf  = (const float*)d_in[2];
    const float* Uf  = (const float*)d_in[3];
    const float* bf  = (const float*)d_in[4];
    const float* Wb  = (const float*)d_in[5];
    const float* Ub  = (const float*)d_in[6];
    const float* bb  = (const float*)d_in[7];
    float* out = (float*)d_out;

    dim3 ggrid(GSZ / 128, (BSZ * TSZ) / 128, 2);
    xz_gemm_kernel<<<ggrid, 256>>>(idx, emb, Wf, bf, Wb, bb);

    const int smem_bytes = 65536 + 131072 + 24576 + 4096;  // 225280
    cudaFuncSetAttribute(lstm_scan_kernel,
                         cudaFuncAttributeMaxDynamicSharedMemorySize, smem_bytes);
    lstm_scan_kernel<<<NBLK, 256, smem_bytes>>>(idx, Uf, Ub, out);
}

// round 11
// speedup vs baseline: 1.4545x; 1.4545x over previous
#include <cuda_runtime.h>
#include <cuda_fp16.h>
#include <cstdint>
#include <math.h>

#define BSZ 64
#define TSZ 512
#define ESZ 256
#define USZ 512
#define GSZ 2048
#define NBLK 128
#define NBLK_DIR 64

// Scratch (static device allocations only)
__device__ float  g_xz[(size_t)2 * TSZ * GSZ * BSZ];      // [dir][t][gc=u*4+g][b]
__device__ __half g_hf[2][2][(size_t)BSZ * USZ];          // [dir][parity][b*512+u]
__device__ unsigned g_bar_cnt[64];                        // [dir*32]
__device__ unsigned g_bar_gen[64];                        // [dir*32]

// ---- packed f32x2 helpers (GEMM1) ----
__device__ __forceinline__ void ffma2(unsigned long long& d, unsigned long long a, unsigned long long b) {
    asm("fma.rn.f32x2 %0, %1, %2, %0;" : "+l"(d) : "l"(a), "l"(b));
}
__device__ __forceinline__ unsigned long long splat2(float x) {
    unsigned long long r; unsigned u = __float_as_uint(x);
    asm("mov.b64 %0, {%1, %1};" : "=l"(r) : "r"(u)); return r;
}
__device__ __forceinline__ void unpack2(unsigned long long v, float& lo, float& hi) {
    unsigned a, b; asm("mov.b64 {%0, %1}, %2;" : "=r"(a), "=r"(b) : "l"(v));
    lo = __uint_as_float(a); hi = __uint_as_float(b);
}
__device__ __forceinline__ float sigf(float x) { return __fdividef(1.f, 1.f + __expf(-x)); }
__device__ __forceinline__ float tanhf_(float x) { return __fdividef(2.f, 1.f + __expf(-2.f * x)) - 1.f; }

// ---- warp-MMA helpers (plain sm_80+ PTX, no 'a'-gated features) ----
__device__ __forceinline__ uint32_t s2u(const void* p) {
    uint32_t a; asm("{.reg .u64 t; cvta.to.shared.u64 t, %1; cvt.u32.u64 %0, t;}" : "=r"(a) : "l"(p));
    return a;
}
__device__ __forceinline__ void ldsm4(uint32_t& r0, uint32_t& r1, uint32_t& r2, uint32_t& r3, uint32_t a) {
    asm volatile("ldmatrix.sync.aligned.m8n8.x4.shared.b16 {%0,%1,%2,%3}, [%4];"
                 : "=r"(r0), "=r"(r1), "=r"(r2), "=r"(r3) : "r"(a));
}
__device__ __forceinline__ void ldsm4t(uint32_t& r0, uint32_t& r1, uint32_t& r2, uint32_t& r3, uint32_t a) {
    asm volatile("ldmatrix.sync.aligned.m8n8.x4.trans.shared.b16 {%0,%1,%2,%3}, [%4];"
                 : "=r"(r0), "=r"(r1), "=r"(r2), "=r"(r3) : "r"(a));
}
__device__ __forceinline__ void mma16816(float* c, uint32_t a0, uint32_t a1, uint32_t a2, uint32_t a3,
                                         uint32_t b0, uint32_t b1) {
    asm volatile("mma.sync.aligned.m16n8k16.row.col.f32.f16.f16.f32 "
                 "{%0,%1,%2,%3}, {%4,%5,%6,%7}, {%8,%9}, {%0,%1,%2,%3};"
                 : "+f"(c[0]), "+f"(c[1]), "+f"(c[2]), "+f"(c[3])
                 : "r"(a0), "r"(a1), "r"(a2), "r"(a3), "r"(b0), "r"(b1));
}

__device__ __forceinline__ void grid_barrier(int dir) {
    __syncthreads();
    if (threadIdx.x == 0) {
        volatile unsigned* gen = &g_bar_gen[dir * 32];
        volatile unsigned* cnt = &g_bar_cnt[dir * 32];
        unsigned g0 = *gen;
        __threadfence();
        unsigned a = atomicAdd(&g_bar_cnt[dir * 32], 1u);
        if (a == NBLK_DIR - 1) {
            *cnt = 0u;
            __threadfence();
            *gen = g0 + 1u;
        } else {
            while (*gen == g0) { }
        }
        __threadfence();
    }
    __syncthreads();
}

// ---------------------------------------------------------------------------
// Kernel 1: xz[dir][t][gc=u*4+g][b] = emb[idx[b][t]] @ W + bias   (fp32)
// ---------------------------------------------------------------------------
__global__ void __launch_bounds__(256) xz_gemm_kernel(
    const int* __restrict__ idx, const float* __restrict__ emb,
    const float* __restrict__ Wf, const float* __restrict__ bf,
    const float* __restrict__ Wb, const float* __restrict__ bb)
{
    const int dir = blockIdx.z;
    const float* __restrict__ W    = dir ? Wb : Wf;
    const float* __restrict__ bias = dir ? bb : bf;
    float* __restrict__ xz = g_xz + (size_t)dir * TSZ * GSZ * BSZ;

    __shared__ float As[16 * 128];
    __shared__ float Bs[16 * 128];
    __shared__ int rowv[128];

    const int tid = threadIdx.x;
    const int rbase = blockIdx.y * 128;
    const int nbase = blockIdx.x * 128;

    if (tid < 128) {
        int r = rbase + tid;
        rowv[tid] = idx[(r & 63) * TSZ + (r >> 6)];
    }
    __syncthreads();

    const int ty = tid >> 4, tx = tid & 15;
    unsigned long long acc2[4][8];
#pragma unroll
    for (int i = 0; i < 4; i++)
#pragma unroll
        for (int j = 0; j < 8; j++) acc2[i][j] = 0ull;

    const int lm = tid >> 1, lkq = (tid & 1) * 8;
    const int lrow = rowv[lm];
    const int lk = tid >> 4, lc = (tid & 15) * 8;

    for (int kt = 0; kt < ESZ; kt += 16) {
        float4 a0 = *(const float4*)&emb[(size_t)lrow * ESZ + kt + lkq];
        float4 a1 = *(const float4*)&emb[(size_t)lrow * ESZ + kt + lkq + 4];
        float4 b0 = *(const float4*)&W[(size_t)(kt + lk) * GSZ + nbase + lc];
        float4 b1 = *(const float4*)&W[(size_t)(kt + lk) * GSZ + nbase + lc + 4];
        As[(lkq + 0) * 128 + lm] = a0.x; As[(lkq + 1) * 128 + lm] = a0.y;
        As[(lkq + 2) * 128 + lm] = a0.z; As[(lkq + 3) * 128 + lm] = a0.w;
        As[(lkq + 4) * 128 + lm] = a1.x; As[(lkq + 5) * 128 + lm] = a1.y;
        As[(lkq + 6) * 128 + lm] = a1.z; As[(lkq + 7) * 128 + lm] = a1.w;
        *(float4*)&Bs[lk * 128 + lc]     = b0;
        *(float4*)&Bs[lk * 128 + lc + 4] = b1;
        __syncthreads();
#pragma unroll
        for (int k = 0; k < 16; ++k) {
            ulonglong2 ra01 = *(const ulonglong2*)&As[k * 128 + ty * 8];
            ulonglong2 ra23 = *(const ulonglong2*)&As[k * 128 + ty * 8 + 4];
            const float* bs = &Bs[k * 128 + tx];
            float bj[8];
#pragma unroll
            for (int j = 0; j < 8; ++j) bj[j] = bs[16 * j];
#pragma unroll
            for (int j = 0; j < 8; ++j) {
                unsigned long long s = splat2(bj[j]);
                ffma2(acc2[0][j], ra01.x, s); ffma2(acc2[1][j], ra01.y, s);
                ffma2(acc2[2][j], ra23.x, s); ffma2(acc2[3][j], ra23.y, s);
            }
        }
        __syncthreads();
    }

    const int r0 = rbase + ty * 8;
    const int t = r0 >> 6, b0 = r0 & 63;
#pragma unroll
    for (int j = 0; j < 8; ++j) {
        int n = nbase + tx + 16 * j;
        int g = n >> 9, u = n & 511;
        int gc = u * 4 + g;
        float bv = bias[n];
        float v[8];
#pragma unroll
        for (int rp = 0; rp < 4; ++rp) {
            float lo, hi; unpack2(acc2[rp][j], lo, hi);
            v[2 * rp] = lo + bv; v[2 * rp + 1] = hi + bv;
        }
        float* p = &xz[((size_t)t * GSZ + gc) * BSZ + b0];
        *(float4*)p       = make_float4(v[0], v[1], v[2], v[3]);
        *(float4*)(p + 4) = make_float4(v[4], v[5], v[6], v[7]);
    }
}

// ---------------------------------------------------------------------------
// Kernel 2: persistent LSTM scan on warp MMA (HMMA fp16 x fp16 -> fp32).
// 128 blocks x 256 thr. Block = (dir, 8 units) -> per step GEMM:
//   Z[b=64][gc=32] = h[b][k=512] @ U[k][gc]
// A = h fp16 smem [64][520], B = U fp16 smem [512][40] (resident).
// 8 warps = 4 M-groups(16b) x 2 N-groups(16gc); 32 k-iters of
// (ldsm4 A, ldsm4t B, 2x mma.m16n8k16). State fp32 in owner registers.
// ---------------------------------------------------------------------------
#define SM_MSK 0
#define SM_AH  4096
#define SM_BU  (4096 + 66560)
#define SM_ZS  (4096 + 66560 + 40960)
#define SMEM_SCAN (4096 + 66560 + 40960 + 9216)   // 120832

__global__ void __launch_bounds__(256) lstm_scan_hmma(
    const int* __restrict__ idx,
    const float* __restrict__ Uf, const float* __restrict__ Ub,
    float* __restrict__ out)
{
    extern __shared__ char smem[];
    unsigned long long* msk = (unsigned long long*)(smem + SM_MSK);
    float* Zs = (float*)(smem + SM_ZS);               // [64][36]
    const uint32_t AH = s2u(smem) + SM_AH;
    const uint32_t BU = s2u(smem) + SM_BU;

    const int tid = threadIdx.x;
    const int dir = blockIdx.x >> 6;
    const int ub  = blockIdx.x & 63;                  // 8 units
    const float* __restrict__ Um = dir ? Ub : Uf;
    const float* __restrict__ xz = g_xz + (size_t)dir * TSZ * GSZ * BSZ;
    __half* __restrict__ hbuf[2] = { g_hf[dir][0], g_hf[dir][1] };

    // --- one-time: U slice -> fp16 smem [k][gc], gc = ul*4+g, row pad 40 ---
    for (int i = tid; i < 512 * 32; i += 256) {
        int k = i >> 5, gc = i & 31;
        int ul = gc >> 2, g = gc & 3;
        float v = Um[(size_t)k * GSZ + g * USZ + ub * 8 + ul];
        *(__half*)(smem + SM_BU + k * 80 + gc * 2) = __float2half(v);
    }
    // --- one-time: masks ---
    for (int tt = tid * 2; tt < tid * 2 + 2; ++tt) {
        unsigned long long m = 0ull;
        for (int b = 0; b < 64; ++b)
            if (idx[b * TSZ + tt] != 0) m |= (1ull << b);
        msk[tt] = m;
    }
    // --- one-time: zero h parity 0 (all blocks of dir write same zeros) ---
    {
        uint4 z = { 0u, 0u, 0u, 0u };
        uint4* p = (uint4*)hbuf[0];
#pragma unroll
        for (int j = 0; j < 16; ++j) p[j * 256 + tid] = z;
    }
    grid_barrier(dir);

    // warp MMA coordinates
    const int w = tid >> 5, l = tid & 31;
    const int mrow = (w & 3) * 16;
    const int ncol = (w >> 2) * 16;
    const uint32_t aBase = AH + (uint32_t)(mrow + (l & 15)) * 1040u + (uint32_t)((l >> 4) * 8) * 2u;
    const uint32_t bBase = BU + (uint32_t)(l & 15) * 80u + (uint32_t)(ncol + (l >> 4) * 8) * 2u;

    // owner mapping: 2 cells per thread
    const int b  = tid & 63;
    const int uq = tid >> 6;                          // 0..3
    float c_st[2] = { 0.f, 0.f }, h_st[2] = { 0.f, 0.f };

    for (int s = 0; s < TSZ; ++s) {
        const int t = dir ? (TSZ - 1 - s) : s;
        const int cur = s & 1, nxt = cur ^ 1;

        // prefetch xz for owned cells: 2 cells x 4 gates
        float xv[2][4];
#pragma unroll
        for (int i = 0; i < 2; ++i) {
            int gc0 = (ub * 8 + uq * 2 + i) * 4;
#pragma unroll
            for (int g = 0; g < 4; ++g)
                xv[i][g] = xz[((size_t)t * GSZ + gc0 + g) * BSZ + b];
        }

        // stage h -> smem A [b][k] fp16, row stride 520 halves
        {
            const uint4* src = (const uint4*)hbuf[cur];
#pragma unroll
            for (int j = 0; j < 16; ++j) {
                int c = j * 256 + tid;
                int bb = c >> 6, u8 = (c & 63) * 8;
                *(uint4*)(smem + SM_AH + bb * 1040 + u8 * 2) = src[c];
            }
        }
        __syncthreads();

        // MMA: 32 k-iters
        float c0[4] = { 0.f, 0.f, 0.f, 0.f };
        float c1[4] = { 0.f, 0.f, 0.f, 0.f };
#pragma unroll 4
        for (int k0 = 0; k0 < 32; ++k0) {
            uint32_t a0, a1, a2, a3, b0r, b1r, b2r, b3r;
            ldsm4(a0, a1, a2, a3, aBase + (uint32_t)k0 * 32u);
            ldsm4t(b0r, b1r, b2r, b3r, bBase + (uint32_t)k0 * 1280u);
            mma16816(c0, a0, a1, a2, a3, b0r, b1r);
            mma16816(c1, a0, a1, a2, a3, b2r, b3r);
        }

        // dump Z frags -> Zs[64][36]
        {
            int row = mrow + (l >> 2);
            int col = ncol + (l & 3) * 2;
            *(float2*)&Zs[row * 36 + col]           = make_float2(c0[0], c0[1]);
            *(float2*)&Zs[(row + 8) * 36 + col]     = make_float2(c0[2], c0[3]);
            *(float2*)&Zs[row * 36 + col + 8]       = make_float2(c1[0], c1[1]);
            *(float2*)&Zs[(row + 8) * 36 + col + 8] = make_float2(c1[2], c1[3]);
        }
        __syncthreads();

        // epilogue: 2 cells per thread
        const bool mv = (msk[t] >> b) & 1ull;
#pragma unroll
        for (int i = 0; i < 2; ++i) {
            int ul = uq * 2 + i;
            float4 z4 = *(const float4*)&Zs[b * 36 + ul * 4];
            float zi = z4.x + xv[i][0];
            float zf = z4.y + xv[i][1];
            float zg = z4.z + xv[i][2];
            float zo = z4.w + xv[i][3];
            float ig = sigf(zi), fg = sigf(zf);
            float gg = tanhf_(zg), og = sigf(zo);
            float cn = fg * c_st[i] + ig * gg;
            float hn = og * tanhf_(cn);
            if (mv) { c_st[i] = cn; h_st[i] = hn; }
            int u = ub * 8 + ul;
            out[((size_t)b * TSZ + t) * 1024 + dir * USZ + u] = h_st[i];
            hbuf[nxt][(size_t)b * USZ + u] = __float2half(h_st[i]);
        }
        grid_barrier(dir);
    }

    // final states
    const size_t H0 = (size_t)BSZ * TSZ * 1024;
    const size_t C0 = H0 + (size_t)BSZ * 1024;
#pragma unroll
    for (int i = 0; i < 2; ++i) {
        int u = ub * 8 + uq * 2 + i;
        out[H0 + (size_t)b * 1024 + dir * USZ + u] = h_st[i];
        out[C0 + (size_t)b * 1024 + dir * USZ + u] = c_st[i];
    }
}

// ---------------------------------------------------------------------------
extern "C" void kernel_launch(void* const* d_in, const int* in_sizes, int n_in,
                              void* d_out, int out_size)
{
    const int*   idx = (const int*)  d_in[0];
    const float* emb = (const float*)d_in[1];
    const float* Wf  = (const float*)d_in[2];
    const float* Uf  = (const float*)d_in[3];
    const float* bf  = (const float*)d_in[4];
    const float* Wb  = (const float*)d_in[5];
    const float* Ub  = (const float*)d_in[6];
    const float* bb  = (const float*)d_in[7];
    float* out = (float*)d_out;

    dim3 ggrid(GSZ / 128, (BSZ * TSZ) / 128, 2);
    xz_gemm_kernel<<<ggrid, 256>>>(idx, emb, Wf, bf, Wb, bb);

    cudaFuncSetAttribute(lstm_scan_hmma,
                         cudaFuncAttributeMaxDynamicSharedMemorySize, SMEM_SCAN);
    lstm_scan_hmma<<<NBLK, 256, SMEM_SCAN>>>(idx, Uf, Ub, out);
}